// round 7
// baseline (speedup 1.0000x reference)
#include <cuda_runtime.h>

#define BATCH   64
#define D_IN    512
#define D_OUT   512
#define GRID_N  100
#define NCHUNK  8
#define CHUNK   (D_IN / NCHUNK)   // 64
#define LN_EPS   1e-5f
#define GRID_EPS 1e-6f

#define ISTRIDE  (D_OUT * GRID_N * 4)   // 204800 floats per i
#define OSTRIDE  (GRID_N * 4)           // 400 floats per o

// ---- scratch (__device__ globals; no allocations allowed) ----
__device__ float g_partial[NCHUNK * BATCH * D_OUT];   // 8.4 MB

// ---------------------------------------------------------------------------
// Fused kernel: LayerNorm (recomputed per CTA) + Bernstein weights + gather.
// grid = (BATCH, NCHUNK), 512 threads (thread = o). blockIdx.x = b (fast) so
// all 64 batches of an i-chunk co-run -> redundant gathers hit L2 (~27MB/chunk
// working set, 2 chunks co-resident < 126MB L2).
// ---------------------------------------------------------------------------
__global__ __launch_bounds__(512, 2) void gather_kernel(
    const float* __restrict__ x,
    const float* __restrict__ ln_w,
    const float* __restrict__ ln_b,
    const float* __restrict__ M,
    const float* __restrict__ poly)
{
    const int b     = blockIdx.x;
    const int chunk = blockIdx.y;
    const int o     = threadIdx.x;
    const int i0    = chunk * CHUNK;

    __shared__ float  red1[16], red2[16];
    __shared__ float  sM[16];
    __shared__ float  sxn[D_IN];     // normalized x for this batch
    __shared__ int    sg[CHUNK];
    __shared__ float4 sw[CHUNK];

    if (o < 16) sM[o] = M[o];

    // ---- LayerNorm over the full row (512 threads, 1 elem each) ----
    const float v = x[b * D_IN + o];
    float s1 = v, s2 = v * v;
    #pragma unroll
    for (int off = 16; off > 0; off >>= 1) {
        s1 += __shfl_xor_sync(0xffffffffu, s1, off);
        s2 += __shfl_xor_sync(0xffffffffu, s2, off);
    }
    if ((o & 31) == 0) { red1[o >> 5] = s1; red2[o >> 5] = s2; }
    __syncthreads();
    if (o < 32) {
        float r1 = (o < 16) ? red1[o] : 0.0f;
        float r2 = (o < 16) ? red2[o] : 0.0f;
        #pragma unroll
        for (int off = 8; off > 0; off >>= 1) {
            r1 += __shfl_xor_sync(0xffffffffu, r1, off);
            r2 += __shfl_xor_sync(0xffffffffu, r2, off);
        }
        if (o == 0) { red1[0] = r1; red2[0] = r2; }
    }
    __syncthreads();

    const float mean = red1[0] * (1.0f / D_IN);
    const float var  = red2[0] * (1.0f / D_IN) - mean * mean;
    const float rstd = rsqrtf(var + LN_EPS);

    // normalized value for this thread's i == o position
    sxn[o] = (v - mean) * rstd * ln_w[o] + ln_b[o];
    __syncthreads();

    // ---- grid index + Bernstein weights for this CTA's 64 i's ----
    if (o < CHUNK) {
        float xn = sxn[i0 + o];
        xn = fminf(fmaxf(xn, -1.0f + GRID_EPS), 1.0f - GRID_EPS);
        xn = (xn + 1.0f) * 0.5f;
        const float scaled = xn * (float)GRID_N;
        int gi = (int)floorf(scaled);
        gi = max(0, min(gi, GRID_N - 1));
        const float tt  = scaled - (float)gi;
        const float tt2 = tt * tt;
        const float tt3 = tt2 * tt;

        float4 w;
        w.x = sM[0] + tt * sM[4] + tt2 * sM[8]  + tt3 * sM[12];
        w.y = sM[1] + tt * sM[5] + tt2 * sM[9]  + tt3 * sM[13];
        w.z = sM[2] + tt * sM[6] + tt2 * sM[10] + tt3 * sM[14];
        w.w = sM[3] + tt * sM[7] + tt2 * sM[11] + tt3 * sM[15];

        sg[o] = gi;
        sw[o] = w;
    }
    __syncthreads();

    // ---- gather + dot4 (proven structure: register acc, unroll-8 MLP) ----
    const float* pbase = poly
        + (size_t)i0 * (size_t)ISTRIDE
        + (size_t)o * OSTRIDE;

    float acc = 0.0f;
    #pragma unroll 8
    for (int ii = 0; ii < CHUNK; ii++) {
        const int    gi = sg[ii];
        const float4 w  = sw[ii];
        const float4 pv = *reinterpret_cast<const float4*>(
            pbase + (size_t)ii * (size_t)ISTRIDE + gi * 4);
        acc += w.x * pv.x + w.y * pv.y + w.z * pv.z + w.w * pv.w;
    }

    g_partial[(chunk * BATCH + b) * D_OUT + o] = acc;
}

// ---------------------------------------------------------------------------
// Reduce partials over 8 chunks. float4, 8 independent loads per thread.
// 64 CTAs x 128 threads = 8192 threads (one per float4 of out).
// ---------------------------------------------------------------------------
__global__ __launch_bounds__(128) void reduce_kernel(float* __restrict__ out)
{
    const int idx4 = blockIdx.x * 128 + threadIdx.x;     // 0..8191
    const float4* p = reinterpret_cast<const float4*>(g_partial) + idx4;

    float4 v[NCHUNK];
    #pragma unroll
    for (int c = 0; c < NCHUNK; c++)
        v[c] = p[(size_t)c * (BATCH * D_OUT / 4)];

    float4 acc;
    acc.x = ((v[0].x + v[1].x) + (v[2].x + v[3].x)) + ((v[4].x + v[5].x) + (v[6].x + v[7].x));
    acc.y = ((v[0].y + v[1].y) + (v[2].y + v[3].y)) + ((v[4].y + v[5].y) + (v[6].y + v[7].y));
    acc.z = ((v[0].z + v[1].z) + (v[2].z + v[3].z)) + ((v[4].z + v[5].z) + (v[6].z + v[7].z));
    acc.w = ((v[0].w + v[1].w) + (v[2].w + v[3].w)) + ((v[4].w + v[5].w) + (v[6].w + v[7].w));

    reinterpret_cast<float4*>(out)[idx4] = acc;
}

// ---------------------------------------------------------------------------
extern "C" void kernel_launch(void* const* d_in, const int* in_sizes, int n_in,
                              void* d_out, int out_size)
{
    const float* x    = (const float*)d_in[0];   // (64, 512)
    const float* poly = (const float*)d_in[1];   // (512, 512, 100, 4)
    const float* ln_w = (const float*)d_in[2];   // (512,)
    const float* ln_b = (const float*)d_in[3];   // (512,)
    const float* M    = (const float*)d_in[4];   // (4, 4)
    float* out = (float*)d_out;                  // (64, 512) fp32

    gather_kernel<<<dim3(BATCH, NCHUNK), D_OUT>>>(x, ln_w, ln_b, M, poly);
    reduce_kernel<<<(BATCH * D_OUT / 4) / 128, 128>>>(out);
}

// round 8
// speedup vs baseline: 1.1217x; 1.1217x over previous
#include <cuda_runtime.h>

#define BATCH   64
#define D_IN    512
#define D_OUT   512
#define GRID_N  100
#define LN_EPS   1e-5f
#define GRID_EPS 1e-6f

#define ICH     32                  // i's per gather CTA
#define NICH    (D_IN / ICH)        // 16 chunks
#define OBL     8                   // o's per gather CTA
#define NOBL    (D_OUT / OBL)       // 64 o-blocks

#define ISTRIDE  (D_OUT * GRID_N * 4)   // 204800 floats per i
#define OSTRIDE  (GRID_N * 4)           // 400 floats per o

// ---- scratch (__device__ globals; no allocations allowed) ----
__device__ int    g_idx_t[D_IN * BATCH];    // transposed: [i][b]
__device__ float4 g_w_t[D_IN * BATCH];      // transposed: [i][b]
__device__ float  g_partial[NICH * BATCH * D_OUT];   // 2.1 MB

// ---------------------------------------------------------------------------
// Kernel 1: LayerNorm + grid index + Bernstein weights (R6-proven), writing
// TRANSPOSED [i][b] so the gather's smem staging is coalesced.
// ---------------------------------------------------------------------------
__global__ __launch_bounds__(128) void prep_kernel(
    const float* __restrict__ x,
    const float* __restrict__ ln_w,
    const float* __restrict__ ln_b,
    const float* __restrict__ M)
{
    const int b = blockIdx.x;
    const int t = threadIdx.x;

    __shared__ float red1[4], red2[4];
    __shared__ float sM[16];
    if (t < 16) sM[t] = M[t];

    const float4 v = reinterpret_cast<const float4*>(x + b * D_IN)[t];

    float s1 = v.x + v.y + v.z + v.w;
    float s2 = v.x * v.x + v.y * v.y + v.z * v.z + v.w * v.w;
    #pragma unroll
    for (int off = 16; off > 0; off >>= 1) {
        s1 += __shfl_xor_sync(0xffffffffu, s1, off);
        s2 += __shfl_xor_sync(0xffffffffu, s2, off);
    }
    if ((t & 31) == 0) { red1[t >> 5] = s1; red2[t >> 5] = s2; }
    __syncthreads();
    if (t < 32) {
        float r1 = (t < 4) ? red1[t] : 0.0f;
        float r2 = (t < 4) ? red2[t] : 0.0f;
        #pragma unroll
        for (int off = 2; off > 0; off >>= 1) {
            r1 += __shfl_xor_sync(0xffffffffu, r1, off);
            r2 += __shfl_xor_sync(0xffffffffu, r2, off);
        }
        if (t == 0) { red1[0] = r1; red2[0] = r2; }
    }
    __syncthreads();

    const float mean = red1[0] * (1.0f / D_IN);
    const float var  = red2[0] * (1.0f / D_IN) - mean * mean;
    const float rstd = rsqrtf(var + LN_EPS);

    const float4 lw = reinterpret_cast<const float4*>(ln_w)[t];
    const float4 lb = reinterpret_cast<const float4*>(ln_b)[t];

    const float vv[4] = { v.x, v.y, v.z, v.w };
    const float ww[4] = { lw.x, lw.y, lw.z, lw.w };
    const float bb[4] = { lb.x, lb.y, lb.z, lb.w };

    #pragma unroll
    for (int j = 0; j < 4; j++) {
        const int i = t * 4 + j;
        float xn = (vv[j] - mean) * rstd * ww[j] + bb[j];
        xn = fminf(fmaxf(xn, -1.0f + GRID_EPS), 1.0f - GRID_EPS);
        xn = (xn + 1.0f) * 0.5f;
        const float scaled = xn * (float)GRID_N;
        int gi = (int)floorf(scaled);
        gi = max(0, min(gi, GRID_N - 1));
        const float tt  = scaled - (float)gi;
        const float tt2 = tt * tt;
        const float tt3 = tt2 * tt;

        float4 w;
        w.x = sM[0] + tt * sM[4] + tt2 * sM[8]  + tt3 * sM[12];
        w.y = sM[1] + tt * sM[5] + tt2 * sM[9]  + tt3 * sM[13];
        w.z = sM[2] + tt * sM[6] + tt2 * sM[10] + tt3 * sM[14];
        w.w = sM[3] + tt * sM[7] + tt2 * sM[11] + tt3 * sM[15];

        g_idx_t[i * BATCH + b] = gi;
        g_w_t  [i * BATCH + b] = w;
    }
}

// ---------------------------------------------------------------------------
// Kernel 2: gather with BATCH on the lanes.
// block = (64 b, 8 o) = 512 thr; warp = 32 consecutive batches at fixed o,
// so each warp-load's 32 addresses fall in one 1600B window (~8-10 lines
// instead of 32). grid = (NOBL=64, NICH=16) = 1024 CTAs.
// ---------------------------------------------------------------------------
__global__ __launch_bounds__(512) void gather_kernel(const float* __restrict__ poly)
{
    const int b  = threadIdx.x;                    // 0..63
    const int ol = threadIdx.y;                    // 0..7
    const int o  = blockIdx.x * OBL + ol;
    const int ch = blockIdx.y;
    const int i0 = ch * ICH;
    const int tid = ol * 64 + b;

    __shared__ int    sg[ICH * BATCH];    // 8 KB
    __shared__ float4 sw[ICH * BATCH];    // 32 KB

    // coalesced staging from transposed arrays
    #pragma unroll
    for (int e = tid; e < ICH * BATCH; e += 512) {
        sg[e] = g_idx_t[i0 * BATCH + e];
        sw[e] = g_w_t  [i0 * BATCH + e];
    }
    __syncthreads();

    const float* pb = poly + (size_t)i0 * ISTRIDE + (size_t)o * OSTRIDE;

    float acc = 0.0f;
    #pragma unroll 8
    for (int ii = 0; ii < ICH; ii++) {
        const int    gi = sg[ii * BATCH + b];
        const float4 w  = sw[ii * BATCH + b];
        const float4 pv = *reinterpret_cast<const float4*>(
            pb + (size_t)ii * ISTRIDE + gi * 4);
        acc += w.x * pv.x + w.y * pv.y + w.z * pv.z + w.w * pv.w;
    }

    g_partial[((size_t)ch * BATCH + b) * D_OUT + o] = acc;
}

// ---------------------------------------------------------------------------
// Kernel 3: reduce partials over 16 chunks. float4, coalesced, MLP=16.
// 8192 threads (one per float4 of out).
// ---------------------------------------------------------------------------
__global__ __launch_bounds__(128) void reduce_kernel(float* __restrict__ out)
{
    const int idx4 = blockIdx.x * 128 + threadIdx.x;     // 0..8191
    const float4* p = reinterpret_cast<const float4*>(g_partial) + idx4;

    float4 v[NICH];
    #pragma unroll
    for (int c = 0; c < NICH; c++)
        v[c] = p[(size_t)c * (BATCH * D_OUT / 4)];

    float4 acc = make_float4(0.f, 0.f, 0.f, 0.f);
    #pragma unroll
    for (int c = 0; c < NICH; c++) {
        acc.x += v[c].x; acc.y += v[c].y;
        acc.z += v[c].z; acc.w += v[c].w;
    }

    reinterpret_cast<float4*>(out)[idx4] = acc;
}

// ---------------------------------------------------------------------------
extern "C" void kernel_launch(void* const* d_in, const int* in_sizes, int n_in,
                              void* d_out, int out_size)
{
    const float* x    = (const float*)d_in[0];   // (64, 512)
    const float* poly = (const float*)d_in[1];   // (512, 512, 100, 4)
    const float* ln_w = (const float*)d_in[2];   // (512,)
    const float* ln_b = (const float*)d_in[3];   // (512,)
    const float* M    = (const float*)d_in[4];   // (4, 4)
    float* out = (float*)d_out;                  // (64, 512) fp32

    prep_kernel<<<BATCH, 128>>>(x, ln_w, ln_b, M);
    gather_kernel<<<dim3(NOBL, NICH), dim3(64, OBL)>>>(poly);
    reduce_kernel<<<(BATCH * D_OUT / 4) / 128, 128>>>(out);
}

// round 9
// speedup vs baseline: 1.1278x; 1.0054x over previous
#include <cuda_runtime.h>

#define BATCH   64
#define D_IN    512
#define D_OUT   512
#define GRID_N  100
#define LN_EPS   1e-5f
#define GRID_EPS 1e-6f

#define ICH     32                  // i's per gather CTA
#define NICH    (D_IN / ICH)        // 16 chunks
#define OBL     8                   // o's per gather CTA
#define NOBL    (D_OUT / OBL)       // 64 o-blocks

#define ISTRIDE  (D_OUT * GRID_N * 4)   // 204800 floats per i
#define OSTRIDE  (GRID_N * 4)           // 400 floats per o

// ---- scratch (__device__ globals; no allocations allowed) ----
__device__ int    g_idx_t[D_IN * BATCH];    // transposed: [i][b]
__device__ float4 g_w_t[D_IN * BATCH];      // transposed: [i][b]
__device__ float  g_partial[NICH * BATCH * D_OUT];   // 2.1 MB

// gather load with L2 128B fetch-promotion: on a miss, pull the whole line.
// Sibling sectors of the line are dense-region cells that other batches /
// the paired warp need -> they become L2 hits instead of extra DRAM trips.
__device__ __forceinline__ float4 ldg_l2_128(const float* p)
{
    float4 v;
    asm("ld.global.nc.L2::128B.v4.f32 {%0,%1,%2,%3}, [%4];"
        : "=f"(v.x), "=f"(v.y), "=f"(v.z), "=f"(v.w)
        : "l"(p));
    return v;
}

// ---------------------------------------------------------------------------
// Kernel 1: LayerNorm + grid index + Bernstein weights, TRANSPOSED [i][b] out.
// ---------------------------------------------------------------------------
__global__ __launch_bounds__(128) void prep_kernel(
    const float* __restrict__ x,
    const float* __restrict__ ln_w,
    const float* __restrict__ ln_b,
    const float* __restrict__ M)
{
    const int b = blockIdx.x;
    const int t = threadIdx.x;

    __shared__ float red1[4], red2[4];
    __shared__ float sM[16];
    if (t < 16) sM[t] = M[t];

    const float4 v = reinterpret_cast<const float4*>(x + b * D_IN)[t];

    float s1 = v.x + v.y + v.z + v.w;
    float s2 = v.x * v.x + v.y * v.y + v.z * v.z + v.w * v.w;
    #pragma unroll
    for (int off = 16; off > 0; off >>= 1) {
        s1 += __shfl_xor_sync(0xffffffffu, s1, off);
        s2 += __shfl_xor_sync(0xffffffffu, s2, off);
    }
    if ((t & 31) == 0) { red1[t >> 5] = s1; red2[t >> 5] = s2; }
    __syncthreads();
    if (t < 32) {
        float r1 = (t < 4) ? red1[t] : 0.0f;
        float r2 = (t < 4) ? red2[t] : 0.0f;
        #pragma unroll
        for (int off = 2; off > 0; off >>= 1) {
            r1 += __shfl_xor_sync(0xffffffffu, r1, off);
            r2 += __shfl_xor_sync(0xffffffffu, r2, off);
        }
        if (t == 0) { red1[0] = r1; red2[0] = r2; }
    }
    __syncthreads();

    const float mean = red1[0] * (1.0f / D_IN);
    const float var  = red2[0] * (1.0f / D_IN) - mean * mean;
    const float rstd = rsqrtf(var + LN_EPS);

    const float4 lw = reinterpret_cast<const float4*>(ln_w)[t];
    const float4 lb = reinterpret_cast<const float4*>(ln_b)[t];

    const float vv[4] = { v.x, v.y, v.z, v.w };
    const float ww[4] = { lw.x, lw.y, lw.z, lw.w };
    const float bb[4] = { lb.x, lb.y, lb.z, lb.w };

    #pragma unroll
    for (int j = 0; j < 4; j++) {
        const int i = t * 4 + j;
        float xn = (vv[j] - mean) * rstd * ww[j] + bb[j];
        xn = fminf(fmaxf(xn, -1.0f + GRID_EPS), 1.0f - GRID_EPS);
        xn = (xn + 1.0f) * 0.5f;
        const float scaled = xn * (float)GRID_N;
        int gi = (int)floorf(scaled);
        gi = max(0, min(gi, GRID_N - 1));
        const float tt  = scaled - (float)gi;
        const float tt2 = tt * tt;
        const float tt3 = tt2 * tt;

        float4 w;
        w.x = sM[0] + tt * sM[4] + tt2 * sM[8]  + tt3 * sM[12];
        w.y = sM[1] + tt * sM[5] + tt2 * sM[9]  + tt3 * sM[13];
        w.z = sM[2] + tt * sM[6] + tt2 * sM[10] + tt3 * sM[14];
        w.w = sM[3] + tt * sM[7] + tt2 * sM[11] + tt3 * sM[15];

        g_idx_t[i * BATCH + b] = gi;
        g_w_t  [i * BATCH + b] = w;
    }
}

// ---------------------------------------------------------------------------
// Kernel 2: gather, BATCH on the lanes (R8 structure, proven 82.8), with
// L2::128B fetch promotion on the scattered poly loads.
// grid = (NOBL=64, NICH=16), block = (64 b, 8 o) = 512 thr.
// ---------------------------------------------------------------------------
__global__ __launch_bounds__(512) void gather_kernel(const float* __restrict__ poly)
{
    const int b  = threadIdx.x;                    // 0..63
    const int ol = threadIdx.y;                    // 0..7
    const int o  = blockIdx.x * OBL + ol;
    const int ch = blockIdx.y;
    const int i0 = ch * ICH;
    const int tid = ol * 64 + b;

    __shared__ int    sg[ICH * BATCH];    // 8 KB
    __shared__ float4 sw[ICH * BATCH];    // 32 KB

    #pragma unroll
    for (int e = tid; e < ICH * BATCH; e += 512) {
        sg[e] = g_idx_t[i0 * BATCH + e];
        sw[e] = g_w_t  [i0 * BATCH + e];
    }
    __syncthreads();

    const float* pb = poly + (size_t)i0 * ISTRIDE + (size_t)o * OSTRIDE;

    float acc = 0.0f;
    #pragma unroll 8
    for (int ii = 0; ii < ICH; ii++) {
        const int    gi = sg[ii * BATCH + b];
        const float4 w  = sw[ii * BATCH + b];
        const float4 pv = ldg_l2_128(pb + (size_t)ii * ISTRIDE + gi * 4);
        acc += w.x * pv.x + w.y * pv.y + w.z * pv.z + w.w * pv.w;
    }

    g_partial[((size_t)ch * BATCH + b) * D_OUT + o] = acc;
}

// ---------------------------------------------------------------------------
// Kernel 3: reduce partials over 16 chunks. float4, coalesced, MLP=16.
// ---------------------------------------------------------------------------
__global__ __launch_bounds__(128) void reduce_kernel(float* __restrict__ out)
{
    const int idx4 = blockIdx.x * 128 + threadIdx.x;     // 0..8191
    const float4* p = reinterpret_cast<const float4*>(g_partial) + idx4;

    float4 v[NICH];
    #pragma unroll
    for (int c = 0; c < NICH; c++)
        v[c] = p[(size_t)c * (BATCH * D_OUT / 4)];

    float4 acc = make_float4(0.f, 0.f, 0.f, 0.f);
    #pragma unroll
    for (int c = 0; c < NICH; c++) {
        acc.x += v[c].x; acc.y += v[c].y;
        acc.z += v[c].z; acc.w += v[c].w;
    }

    reinterpret_cast<float4*>(out)[idx4] = acc;
}

// ---------------------------------------------------------------------------
extern "C" void kernel_launch(void* const* d_in, const int* in_sizes, int n_in,
                              void* d_out, int out_size)
{
    const float* x    = (const float*)d_in[0];   // (64, 512)
    const float* poly = (const float*)d_in[1];   // (512, 512, 100, 4)
    const float* ln_w = (const float*)d_in[2];   // (512,)
    const float* ln_b = (const float*)d_in[3];   // (512,)
    const float* M    = (const float*)d_in[4];   // (4, 4)
    float* out = (float*)d_out;                  // (64, 512) fp32

    prep_kernel<<<BATCH, 128>>>(x, ln_w, ln_b, M);
    gather_kernel<<<dim3(NOBL, NICH), dim3(64, OBL)>>>(poly);
    reduce_kernel<<<(BATCH * D_OUT / 4) / 128, 128>>>(out);
}

// round 10
// speedup vs baseline: 1.1362x; 1.0074x over previous
#include <cuda_runtime.h>

#define BATCH   64
#define D_IN    512
#define D_OUT   512
#define GRID_N  100
#define LN_EPS   1e-5f
#define GRID_EPS 1e-6f

#define ICH     32                  // i's per gather CTA
#define NICH    (D_IN / ICH)        // 16 chunks
#define OBL     8                   // o's per gather CTA
#define NOBL    (D_OUT / OBL)       // 64 o-blocks

#define ISTRIDE  (D_OUT * GRID_N * 4)   // 204800 floats per i
#define OSTRIDE  (GRID_N * 4)           // 400 floats per o

// ---- scratch (__device__ globals; no allocations allowed) ----
__device__ int    g_idx_t[D_IN * BATCH];    // transposed: [i][b]
__device__ float4 g_w_t[D_IN * BATCH];      // transposed: [i][b]
__device__ float  g_partial[NICH * BATCH * D_OUT];   // 2.1 MB

__device__ __forceinline__ float4 ldg_nc(const float* p)
{
    float4 v;
    asm("ld.global.nc.v4.f32 {%0,%1,%2,%3}, [%4];"
        : "=f"(v.x), "=f"(v.y), "=f"(v.z), "=f"(v.w)
        : "l"(p));
    return v;
}

// ---------------------------------------------------------------------------
// Kernel 1: LayerNorm + grid index + Bernstein weights, TRANSPOSED [i][b] out.
// ---------------------------------------------------------------------------
__global__ __launch_bounds__(128) void prep_kernel(
    const float* __restrict__ x,
    const float* __restrict__ ln_w,
    const float* __restrict__ ln_b,
    const float* __restrict__ M)
{
    const int b = blockIdx.x;
    const int t = threadIdx.x;

    __shared__ float red1[4], red2[4];
    __shared__ float sM[16];
    if (t < 16) sM[t] = M[t];

    const float4 v = reinterpret_cast<const float4*>(x + b * D_IN)[t];

    float s1 = v.x + v.y + v.z + v.w;
    float s2 = v.x * v.x + v.y * v.y + v.z * v.z + v.w * v.w;
    #pragma unroll
    for (int off = 16; off > 0; off >>= 1) {
        s1 += __shfl_xor_sync(0xffffffffu, s1, off);
        s2 += __shfl_xor_sync(0xffffffffu, s2, off);
    }
    if ((t & 31) == 0) { red1[t >> 5] = s1; red2[t >> 5] = s2; }
    __syncthreads();
    if (t < 32) {
        float r1 = (t < 4) ? red1[t] : 0.0f;
        float r2 = (t < 4) ? red2[t] : 0.0f;
        #pragma unroll
        for (int off = 2; off > 0; off >>= 1) {
            r1 += __shfl_xor_sync(0xffffffffu, r1, off);
            r2 += __shfl_xor_sync(0xffffffffu, r2, off);
        }
        if (t == 0) { red1[0] = r1; red2[0] = r2; }
    }
    __syncthreads();

    const float mean = red1[0] * (1.0f / D_IN);
    const float var  = red2[0] * (1.0f / D_IN) - mean * mean;
    const float rstd = rsqrtf(var + LN_EPS);

    const float4 lw = reinterpret_cast<const float4*>(ln_w)[t];
    const float4 lb = reinterpret_cast<const float4*>(ln_b)[t];

    const float vv[4] = { v.x, v.y, v.z, v.w };
    const float ww[4] = { lw.x, lw.y, lw.z, lw.w };
    const float bb[4] = { lb.x, lb.y, lb.z, lb.w };

    #pragma unroll
    for (int j = 0; j < 4; j++) {
        const int i = t * 4 + j;
        float xn = (vv[j] - mean) * rstd * ww[j] + bb[j];
        xn = fminf(fmaxf(xn, -1.0f + GRID_EPS), 1.0f - GRID_EPS);
        xn = (xn + 1.0f) * 0.5f;
        const float scaled = xn * (float)GRID_N;
        int gi = (int)floorf(scaled);
        gi = max(0, min(gi, GRID_N - 1));
        const float tt  = scaled - (float)gi;
        const float tt2 = tt * tt;
        const float tt3 = tt2 * tt;

        float4 w;
        w.x = sM[0] + tt * sM[4] + tt2 * sM[8]  + tt3 * sM[12];
        w.y = sM[1] + tt * sM[5] + tt2 * sM[9]  + tt3 * sM[13];
        w.z = sM[2] + tt * sM[6] + tt2 * sM[10] + tt3 * sM[14];
        w.w = sM[3] + tt * sM[7] + tt2 * sM[11] + tt3 * sM[15];

        g_idx_t[i * BATCH + b] = gi;
        g_w_t  [i * BATCH + b] = w;
    }
}

// ---------------------------------------------------------------------------
// Kernel 2: gather, BATCH on the lanes (proven structure). PDL: launched
// while prep drains; blocks on grid dependency before touching prep output.
// grid = (NOBL=64, NICH=16), block = (64 b, 8 o) = 512 thr.
// ---------------------------------------------------------------------------
__global__ __launch_bounds__(512) void gather_kernel(const float* __restrict__ poly)
{
    const int b  = threadIdx.x;                    // 0..63
    const int ol = threadIdx.y;                    // 0..7
    const int o  = blockIdx.x * OBL + ol;
    const int ch = blockIdx.y;
    const int i0 = ch * ICH;
    const int tid = ol * 64 + b;

    __shared__ int    sg[ICH * BATCH];    // 8 KB
    __shared__ float4 sw[ICH * BATCH];    // 32 KB

    // pre-sync work: address setup only
    const float* pb = poly + (size_t)i0 * ISTRIDE + (size_t)o * OSTRIDE;

    // wait for prep_kernel's writes to be visible
    cudaGridDependencySynchronize();

    #pragma unroll
    for (int e = tid; e < ICH * BATCH; e += 512) {
        sg[e] = g_idx_t[i0 * BATCH + e];
        sw[e] = g_w_t  [i0 * BATCH + e];
    }
    __syncthreads();

    float acc = 0.0f;
    #pragma unroll 8
    for (int ii = 0; ii < ICH; ii++) {
        const int    gi = sg[ii * BATCH + b];
        const float4 w  = sw[ii * BATCH + b];
        const float4 pv = ldg_nc(pb + (size_t)ii * ISTRIDE + gi * 4);
        acc += w.x * pv.x + w.y * pv.y + w.z * pv.z + w.w * pv.w;
    }

    g_partial[((size_t)ch * BATCH + b) * D_OUT + o] = acc;
}

// ---------------------------------------------------------------------------
// Kernel 3: reduce partials over 16 chunks. PDL-overlapped launch.
// ---------------------------------------------------------------------------
__global__ __launch_bounds__(128) void reduce_kernel(float* __restrict__ out)
{
    const int idx4 = blockIdx.x * 128 + threadIdx.x;     // 0..8191
    const float4* p = reinterpret_cast<const float4*>(g_partial) + idx4;

    cudaGridDependencySynchronize();

    float4 v[NICH];
    #pragma unroll
    for (int c = 0; c < NICH; c++)
        v[c] = p[(size_t)c * (BATCH * D_OUT / 4)];

    float4 acc = make_float4(0.f, 0.f, 0.f, 0.f);
    #pragma unroll
    for (int c = 0; c < NICH; c++) {
        acc.x += v[c].x; acc.y += v[c].y;
        acc.z += v[c].z; acc.w += v[c].w;
    }

    reinterpret_cast<float4*>(out)[idx4] = acc;
}

// ---------------------------------------------------------------------------
extern "C" void kernel_launch(void* const* d_in, const int* in_sizes, int n_in,
                              void* d_out, int out_size)
{
    const float* x    = (const float*)d_in[0];   // (64, 512)
    const float* poly = (const float*)d_in[1];   // (512, 512, 100, 4)
    const float* ln_w = (const float*)d_in[2];   // (512,)
    const float* ln_b = (const float*)d_in[3];   // (512,)
    const float* M    = (const float*)d_in[4];   // (4, 4)
    float* out = (float*)d_out;                  // (64, 512) fp32

    // kernel 1: normal launch
    prep_kernel<<<BATCH, 128>>>(x, ln_w, ln_b, M);

    // kernel 2: PDL — launch overlaps prep's drain
    {
        cudaLaunchConfig_t cfg = {};
        cfg.gridDim  = dim3(NOBL, NICH);
        cfg.blockDim = dim3(64, OBL);
        cudaLaunchAttribute attr[1];
        attr[0].id = cudaLaunchAttributeProgrammaticStreamSerialization;
        attr[0].val.programmaticStreamSerializationAllowed = 1;
        cfg.attrs = attr;
        cfg.numAttrs = 1;
        cudaLaunchKernelEx(&cfg, gather_kernel, poly);
    }

    // kernel 3: PDL — launch overlaps gather's drain
    {
        cudaLaunchConfig_t cfg = {};
        cfg.gridDim  = dim3((BATCH * D_OUT / 4) / 128);
        cfg.blockDim = dim3(128);
        cudaLaunchAttribute attr[1];
        attr[0].id = cudaLaunchAttributeProgrammaticStreamSerialization;
        attr[0].val.programmaticStreamSerializationAllowed = 1;
        cfg.attrs = attr;
        cfg.numAttrs = 1;
        cudaLaunchKernelEx(&cfg, reduce_kernel, out);
    }
}

// round 12
// speedup vs baseline: 1.1931x; 1.0501x over previous
#include <cuda_runtime.h>
#include <cstdint>

#define BATCH   64
#define D_IN    512
#define D_OUT   512
#define GRID_N  100
#define LN_EPS   1e-5f
#define GRID_EPS 1e-6f

#define ICH     32                  // i's per gather CTA
#define NICH    (D_IN / ICH)        // 16 chunks
#define OBL     8                   // o's per gather CTA
#define NOBL    (D_OUT / OBL)       // 64 o-blocks

#define ISTRIDE  (D_OUT * GRID_N * 4)   // 204800 floats per i
#define OSTRIDE  (GRID_N * 4)           // 400 floats per o
#define TILE_FLOATS (OBL * OSTRIDE)     // 3200 floats = 12.8 KB, contiguous
#define TILE_U4     (TILE_FLOATS / 4)   // 800 16B chunks

// ---- scratch (__device__ globals; no allocations allowed) ----
__device__ float g_scaled[D_IN * BATCH];             // transposed [i][b]
__device__ float g_partial[NICH * BATCH * D_OUT];    // 2.1 MB

// ---- cp.async helpers ----
__device__ __forceinline__ void cp16(void* sdst, const void* gsrc)
{
    unsigned int a = (unsigned int)__cvta_generic_to_shared(sdst);
    asm volatile("cp.async.cg.shared.global [%0], [%1], 16;"
                 :: "r"(a), "l"(gsrc));
}
#define CP_COMMIT() asm volatile("cp.async.commit_group;" ::: "memory")
#define CP_WAIT1()  asm volatile("cp.async.wait_group 1;" ::: "memory")

// ---------------------------------------------------------------------------
// Kernel 1: LayerNorm -> clamped scaled coordinate (floor/frac done in gather).
// One CTA per batch, 128 threads, float4 per thread.
// ---------------------------------------------------------------------------
__global__ __launch_bounds__(128) void prep_kernel(
    const float* __restrict__ x,
    const float* __restrict__ ln_w,
    const float* __restrict__ ln_b)
{
    const int b = blockIdx.x;
    const int t = threadIdx.x;

    __shared__ float red1[4], red2[4];

    const float4 v = reinterpret_cast<const float4*>(x + b * D_IN)[t];

    float s1 = v.x + v.y + v.z + v.w;
    float s2 = v.x * v.x + v.y * v.y + v.z * v.z + v.w * v.w;
    #pragma unroll
    for (int off = 16; off > 0; off >>= 1) {
        s1 += __shfl_xor_sync(0xffffffffu, s1, off);
        s2 += __shfl_xor_sync(0xffffffffu, s2, off);
    }
    if ((t & 31) == 0) { red1[t >> 5] = s1; red2[t >> 5] = s2; }
    __syncthreads();
    if (t < 32) {
        float r1 = (t < 4) ? red1[t] : 0.0f;
        float r2 = (t < 4) ? red2[t] : 0.0f;
        #pragma unroll
        for (int off = 2; off > 0; off >>= 1) {
            r1 += __shfl_xor_sync(0xffffffffu, r1, off);
            r2 += __shfl_xor_sync(0xffffffffu, r2, off);
        }
        if (t == 0) { red1[0] = r1; red2[0] = r2; }
    }
    __syncthreads();

    const float mean = red1[0] * (1.0f / D_IN);
    const float var  = red2[0] * (1.0f / D_IN) - mean * mean;
    const float rstd = rsqrtf(var + LN_EPS);

    const float4 lw = reinterpret_cast<const float4*>(ln_w)[t];
    const float4 lb = reinterpret_cast<const float4*>(ln_b)[t];

    const float vv[4] = { v.x, v.y, v.z, v.w };
    const float ww[4] = { lw.x, lw.y, lw.z, lw.w };
    const float bb[4] = { lb.x, lb.y, lb.z, lb.w };

    #pragma unroll
    for (int j = 0; j < 4; j++) {
        const int i = t * 4 + j;
        float xn = (vv[j] - mean) * rstd * ww[j] + bb[j];
        xn = fminf(fmaxf(xn, -1.0f + GRID_EPS), 1.0f - GRID_EPS);
        xn = (xn + 1.0f) * 0.5f;
        g_scaled[i * BATCH + b] = xn * (float)GRID_N;   // in [0, 100)
    }
}

// ---------------------------------------------------------------------------
// Kernel 2: DENSE-STREAMING evaluation. Each CTA owns 8 o's x 32 i's; for
// each i it streams the contiguous 12.8KB tile poly[i][o0:o0+8][:][:] into
// smem via a depth-2 cp.async pipeline, then every thread (b, o) picks its
// grid cell from smem. Converts the random-32B-sector gather (3.5 TB/s
// ceiling) into a pure dense stream (~6.8 TB/s). PDL pre-sync prefetches the
// first two tiles while prep drains.
// grid = (NOBL=64, NICH=16), block = (64 b, 8 o) = 512 thr.
// ---------------------------------------------------------------------------
__global__ __launch_bounds__(512) void gather_kernel(
    const float* __restrict__ poly,
    const float* __restrict__ M)
{
    const int b   = threadIdx.x;                 // 0..63
    const int ol  = threadIdx.y;                 // 0..7
    const int ch  = blockIdx.y;
    const int i0  = ch * ICH;
    const int tid = ol * 64 + b;

    __shared__ float buf[2][TILE_FLOATS];        // 25.6 KB
    __shared__ float ssc[ICH * BATCH];           // 8 KB
    __shared__ float sM[16];

    const float* tb = poly + (size_t)i0 * ISTRIDE
                           + (size_t)blockIdx.x * TILE_FLOATS;

    // ---- PDL pre-sync region: independent of prep ----
    if (tid < 16) sM[tid] = M[tid];

    {   // prefetch tiles 0 and 1
        const float* s0 = tb;
        if (tid < TILE_U4)        cp16(&buf[0][tid * 4],         s0 + tid * 4);
        if (tid + 512 < TILE_U4)  cp16(&buf[0][(tid + 512) * 4], s0 + (tid + 512) * 4);
        CP_COMMIT();
        const float* s1 = tb + ISTRIDE;
        if (tid < TILE_U4)        cp16(&buf[1][tid * 4],         s1 + tid * 4);
        if (tid + 512 < TILE_U4)  cp16(&buf[1][(tid + 512) * 4], s1 + (tid + 512) * 4);
        CP_COMMIT();
    }

    // ---- wait for prep's g_scaled ----
    cudaGridDependencySynchronize();

    for (int e = tid; e < ICH * BATCH; e += 512)
        ssc[e] = g_scaled[i0 * BATCH + e];
    __syncthreads();

    float acc = 0.0f;

    #pragma unroll 2
    for (int ii = 0; ii < ICH; ii++) {
        CP_WAIT1();          // tile ii landed
        __syncthreads();     // visible to all threads

        const float sc = ssc[ii * BATCH + b];
        int gi = (int)sc;                       // sc >= 0 -> trunc == floor
        gi = min(gi, GRID_N - 1);
        const float t  = sc - (float)gi;
        const float t2 = t * t;
        const float t3 = t2 * t;

        float4 w;
        w.x = sM[0] + t * sM[4] + t2 * sM[8]  + t3 * sM[12];
        w.y = sM[1] + t * sM[5] + t2 * sM[9]  + t3 * sM[13];
        w.z = sM[2] + t * sM[6] + t2 * sM[10] + t3 * sM[14];
        w.w = sM[3] + t * sM[7] + t2 * sM[11] + t3 * sM[15];

        const float4 pv = *reinterpret_cast<const float4*>(
            &buf[ii & 1][ol * OSTRIDE + gi * 4]);
        acc += w.x * pv.x + w.y * pv.y + w.z * pv.z + w.w * pv.w;

        __syncthreads();     // everyone done reading buf[ii&1]

        // prefetch tile ii+2 into the buffer just freed
        if (ii + 2 < ICH) {
            const float* s = tb + (size_t)(ii + 2) * ISTRIDE;
            if (tid < TILE_U4)        cp16(&buf[ii & 1][tid * 4],         s + tid * 4);
            if (tid + 512 < TILE_U4)  cp16(&buf[ii & 1][(tid + 512) * 4], s + (tid + 512) * 4);
        }
        CP_COMMIT();         // always commit (possibly empty) -> group counts stay aligned
    }

    const int o = blockIdx.x * OBL + ol;
    g_partial[((size_t)ch * BATCH + b) * D_OUT + o] = acc;
}

// ---------------------------------------------------------------------------
// Kernel 3: reduce partials over 16 chunks (PDL-overlapped).
// ---------------------------------------------------------------------------
__global__ __launch_bounds__(128) void reduce_kernel(float* __restrict__ out)
{
    const int idx4 = blockIdx.x * 128 + threadIdx.x;     // 0..8191
    const float4* p = reinterpret_cast<const float4*>(g_partial) + idx4;

    cudaGridDependencySynchronize();

    float4 v[NICH];
    #pragma unroll
    for (int c = 0; c < NICH; c++)
        v[c] = p[(size_t)c * (BATCH * D_OUT / 4)];

    float4 acc = make_float4(0.f, 0.f, 0.f, 0.f);
    #pragma unroll
    for (int c = 0; c < NICH; c++) {
        acc.x += v[c].x; acc.y += v[c].y;
        acc.z += v[c].z; acc.w += v[c].w;
    }

    reinterpret_cast<float4*>(out)[idx4] = acc;
}

// ---------------------------------------------------------------------------
extern "C" void kernel_launch(void* const* d_in, const int* in_sizes, int n_in,
                              void* d_out, int out_size)
{
    const float* x    = (const float*)d_in[0];   // (64, 512)
    const float* poly = (const float*)d_in[1];   // (512, 512, 100, 4)
    const float* ln_w = (const float*)d_in[2];   // (512,)
    const float* ln_b = (const float*)d_in[3];   // (512,)
    const float* M    = (const float*)d_in[4];   // (4, 4)
    float* out = (float*)d_out;                  // (64, 512) fp32

    prep_kernel<<<BATCH, 128>>>(x, ln_w, ln_b);

    {   // gather: PDL — pre-sync tile prefetch overlaps prep
        cudaLaunchConfig_t cfg = {};
        cfg.gridDim  = dim3(NOBL, NICH);
        cfg.blockDim = dim3(64, OBL);
        cudaLaunchAttribute attr[1];
        attr[0].id = cudaLaunchAttributeProgrammaticStreamSerialization;
        attr[0].val.programmaticStreamSerializationAllowed = 1;
        cfg.attrs = attr;
        cfg.numAttrs = 1;
        cudaLaunchKernelEx(&cfg, gather_kernel, poly, M);
    }

    {   // reduce: PDL — overlaps gather's drain
        cudaLaunchConfig_t cfg = {};
        cfg.gridDim  = dim3((BATCH * D_OUT / 4) / 128);
        cfg.blockDim = dim3(128);
        cudaLaunchAttribute attr[1];
        attr[0].id = cudaLaunchAttributeProgrammaticStreamSerialization;
        attr[0].val.programmaticStreamSerializationAllowed = 1;
        cfg.attrs = attr;
        cfg.numAttrs = 1;
        cudaLaunchKernelEx(&cfg, reduce_kernel, out);
    }
}

// round 13
// speedup vs baseline: 1.2269x; 1.0283x over previous
#include <cuda_runtime.h>
#include <cstdint>

#define BATCH   64
#define D_IN    512
#define D_OUT   512
#define GRID_N  100
#define LN_EPS   1e-5f
#define GRID_EPS 1e-6f

#define ICH     32                  // i's per gather CTA
#define NICH    (D_IN / ICH)        // 16 chunks
#define OBL     8                   // o's per gather CTA
#define NOBL    (D_OUT / OBL)       // 64 o-blocks
#define NSTAGE  3                   // pipeline depth (smem buffers)

#define ISTRIDE  (D_OUT * GRID_N * 4)   // 204800 floats per i
#define OSTRIDE  (GRID_N * 4)           // 400 floats per o
#define TILE_FLOATS (OBL * OSTRIDE)     // 3200 floats = 12.8 KB, contiguous
#define TILE_U4     (TILE_FLOATS / 4)   // 800 16B chunks

// ---- scratch (__device__ globals; no allocations allowed) ----
__device__ float g_scaled[D_IN * BATCH];             // transposed [i][b]
__device__ float g_partial[NICH * BATCH * D_OUT];    // 2.1 MB

// ---- cp.async / griddep helpers ----
__device__ __forceinline__ void cp16(void* sdst, const void* gsrc)
{
    unsigned int a = (unsigned int)__cvta_generic_to_shared(sdst);
    asm volatile("cp.async.cg.shared.global [%0], [%1], 16;"
                 :: "r"(a), "l"(gsrc));
}
#define CP_COMMIT()   asm volatile("cp.async.commit_group;" ::: "memory")
#define CP_WAIT1()    asm volatile("cp.async.wait_group 1;" ::: "memory")
#define GDC_TRIGGER() asm volatile("griddepcontrol.launch_dependents;" ::: "memory")
#define GDC_WAIT()    asm volatile("griddepcontrol.wait;" ::: "memory")

// ---------------------------------------------------------------------------
// Kernel 1: LayerNorm -> clamped scaled coordinate. Triggers dependent launch
// immediately so the gather grid's cp.async prefetches overlap this kernel.
// ---------------------------------------------------------------------------
__global__ __launch_bounds__(128) void prep_kernel(
    const float* __restrict__ x,
    const float* __restrict__ ln_w,
    const float* __restrict__ ln_b)
{
    GDC_TRIGGER();   // let gather CTAs launch + prefetch now

    const int b = blockIdx.x;
    const int t = threadIdx.x;

    __shared__ float red1[4], red2[4];

    const float4 v = reinterpret_cast<const float4*>(x + b * D_IN)[t];

    float s1 = v.x + v.y + v.z + v.w;
    float s2 = v.x * v.x + v.y * v.y + v.z * v.z + v.w * v.w;
    #pragma unroll
    for (int off = 16; off > 0; off >>= 1) {
        s1 += __shfl_xor_sync(0xffffffffu, s1, off);
        s2 += __shfl_xor_sync(0xffffffffu, s2, off);
    }
    if ((t & 31) == 0) { red1[t >> 5] = s1; red2[t >> 5] = s2; }
    __syncthreads();
    if (t < 32) {
        float r1 = (t < 4) ? red1[t] : 0.0f;
        float r2 = (t < 4) ? red2[t] : 0.0f;
        #pragma unroll
        for (int off = 2; off > 0; off >>= 1) {
            r1 += __shfl_xor_sync(0xffffffffu, r1, off);
            r2 += __shfl_xor_sync(0xffffffffu, r2, off);
        }
        if (t == 0) { red1[0] = r1; red2[0] = r2; }
    }
    __syncthreads();

    const float mean = red1[0] * (1.0f / D_IN);
    const float var  = red2[0] * (1.0f / D_IN) - mean * mean;
    const float rstd = rsqrtf(var + LN_EPS);

    const float4 lw = reinterpret_cast<const float4*>(ln_w)[t];
    const float4 lb = reinterpret_cast<const float4*>(ln_b)[t];

    const float vv[4] = { v.x, v.y, v.z, v.w };
    const float ww[4] = { lw.x, lw.y, lw.z, lw.w };
    const float bb[4] = { lb.x, lb.y, lb.z, lb.w };

    #pragma unroll
    for (int j = 0; j < 4; j++) {
        const int i = t * 4 + j;
        float xn = (vv[j] - mean) * rstd * ww[j] + bb[j];
        xn = fminf(fmaxf(xn, -1.0f + GRID_EPS), 1.0f - GRID_EPS);
        xn = (xn + 1.0f) * 0.5f;
        g_scaled[i * BATCH + b] = xn * (float)GRID_N;   // in [0, 100)
    }
}

// ---------------------------------------------------------------------------
// Kernel 2: dense-streaming evaluation, 3-stage cp.async pipeline with ONE
// __syncthreads per tile. grid = (NOBL=64, NICH=16), block = (64 b, 8 o).
// ---------------------------------------------------------------------------
__global__ __launch_bounds__(512) void gather_kernel(
    const float* __restrict__ poly,
    const float* __restrict__ M)
{
    const int b   = threadIdx.x;                 // 0..63
    const int ol  = threadIdx.y;                 // 0..7
    const int ch  = blockIdx.y;
    const int i0  = ch * ICH;
    const int tid = ol * 64 + b;

    __shared__ float buf[NSTAGE][TILE_FLOATS];   // 38.4 KB
    __shared__ float ssc[ICH * BATCH];           // 8 KB
    __shared__ float sM[16];

    const float* tb = poly + (size_t)i0 * ISTRIDE
                           + (size_t)blockIdx.x * TILE_FLOATS;

    // ---- PDL pre-sync region: prefetch tiles 0,1 (independent of prep) ----
    if (tid < 16) sM[tid] = M[tid];
    {
        const float* s0 = tb;
        if (tid < TILE_U4)        cp16(&buf[0][tid * 4],         s0 + tid * 4);
        if (tid + 512 < TILE_U4)  cp16(&buf[0][(tid + 512) * 4], s0 + (tid + 512) * 4);
        CP_COMMIT();
        const float* s1 = tb + ISTRIDE;
        if (tid < TILE_U4)        cp16(&buf[1][tid * 4],         s1 + tid * 4);
        if (tid + 512 < TILE_U4)  cp16(&buf[1][(tid + 512) * 4], s1 + (tid + 512) * 4);
        CP_COMMIT();
    }

    // ---- wait for prep's g_scaled ----
    GDC_WAIT();

    for (int e = tid; e < ICH * BATCH; e += 512)
        ssc[e] = g_scaled[i0 * BATCH + e];
    // (no explicit sync: the loop's first __syncthreads covers ssc visibility)

    float acc = 0.0f;

    for (int ii = 0; ii < ICH; ii++) {
        CP_WAIT1();          // <=1 group pending -> tile ii landed
        __syncthreads();     // tile ii visible; everyone done with iter ii-1

        const float sc = ssc[ii * BATCH + b];
        int gi = (int)sc;                       // sc >= 0 -> trunc == floor
        gi = min(gi, GRID_N - 1);
        const float t  = sc - (float)gi;
        const float t2 = t * t;
        const float t3 = t2 * t;

        float4 w;
        w.x = sM[0] + t * sM[4] + t2 * sM[8]  + t3 * sM[12];
        w.y = sM[1] + t * sM[5] + t2 * sM[9]  + t3 * sM[13];
        w.z = sM[2] + t * sM[6] + t2 * sM[10] + t3 * sM[14];
        w.w = sM[3] + t * sM[7] + t2 * sM[11] + t3 * sM[15];

        const float4 pv = *reinterpret_cast<const float4*>(
            &buf[ii % NSTAGE][ol * OSTRIDE + gi * 4]);
        acc += w.x * pv.x + w.y * pv.y + w.z * pv.z + w.w * pv.w;

        // prefetch tile ii+2 into buf[(ii+2)%3] (= buffer read in iter ii-1;
        // safe: the sync above proves all threads finished iter ii-1)
        if (ii + 2 < ICH) {
            const float* s = tb + (size_t)(ii + 2) * ISTRIDE;
            float* d = buf[(ii + 2) % NSTAGE];
            if (tid < TILE_U4)        cp16(&d[tid * 4],         s + tid * 4);
            if (tid + 512 < TILE_U4)  cp16(&d[(tid + 512) * 4], s + (tid + 512) * 4);
        }
        CP_COMMIT();         // always commit -> group counting stays aligned
    }

    const int o = blockIdx.x * OBL + ol;
    g_partial[((size_t)ch * BATCH + b) * D_OUT + o] = acc;
}

// ---------------------------------------------------------------------------
// Kernel 3: reduce partials over 16 chunks (PDL-overlapped).
// ---------------------------------------------------------------------------
__global__ __launch_bounds__(128) void reduce_kernel(float* __restrict__ out)
{
    const int idx4 = blockIdx.x * 128 + threadIdx.x;     // 0..8191
    const float4* p = reinterpret_cast<const float4*>(g_partial) + idx4;

    GDC_WAIT();

    float4 v[NICH];
    #pragma unroll
    for (int c = 0; c < NICH; c++)
        v[c] = p[(size_t)c * (BATCH * D_OUT / 4)];

    float4 acc = make_float4(0.f, 0.f, 0.f, 0.f);
    #pragma unroll
    for (int c = 0; c < NICH; c++) {
        acc.x += v[c].x; acc.y += v[c].y;
        acc.z += v[c].z; acc.w += v[c].w;
    }

    reinterpret_cast<float4*>(out)[idx4] = acc;
}

// ---------------------------------------------------------------------------
extern "C" void kernel_launch(void* const* d_in, const int* in_sizes, int n_in,
                              void* d_out, int out_size)
{
    const float* x    = (const float*)d_in[0];   // (64, 512)
    const float* poly = (const float*)d_in[1];   // (512, 512, 100, 4)
    const float* ln_w = (const float*)d_in[2];   // (512,)
    const float* ln_b = (const float*)d_in[3];   // (512,)
    const float* M    = (const float*)d_in[4];   // (4, 4)
    float* out = (float*)d_out;                  // (64, 512) fp32

    prep_kernel<<<BATCH, 128>>>(x, ln_w, ln_b);

    {   // gather: PDL — prefetch overlaps prep (early trigger in prep)
        cudaLaunchConfig_t cfg = {};
        cfg.gridDim  = dim3(NOBL, NICH);
        cfg.blockDim = dim3(64, OBL);
        cudaLaunchAttribute attr[1];
        attr[0].id = cudaLaunchAttributeProgrammaticStreamSerialization;
        attr[0].val.programmaticStreamSerializationAllowed = 1;
        cfg.attrs = attr;
        cfg.numAttrs = 1;
        cudaLaunchKernelEx(&cfg, gather_kernel, poly, M);
    }

    {   // reduce: PDL — overlaps gather's drain
        cudaLaunchConfig_t cfg = {};
        cfg.gridDim  = dim3((BATCH * D_OUT / 4) / 128);
        cfg.blockDim = dim3(128);
        cudaLaunchAttribute attr[1];
        attr[0].id = cudaLaunchAttributeProgrammaticStreamSerialization;
        attr[0].val.programmaticStreamSerializationAllowed = 1;
        cfg.attrs = attr;
        cfg.numAttrs = 1;
        cudaLaunchKernelEx(&cfg, reduce_kernel, out);
    }
}